// round 13
// baseline (speedup 1.0000x reference)
#include <cuda_runtime.h>
#include <cuda_fp16.h>
#include <math.h>
#include <stdint.h>

#define VOCAB   32000
#define EMBED   512
#define HIDDEN  1024
#define G4      4096
#define BATCH   64
#define SRCLEN  1024
#define NCTA    128

// Scratch (device globals)
__device__ __half   d_xp16[(size_t)SRCLEN * BATCH * G4];    // (t,b,g) fp16
__device__ __half   d_emb16[(size_t)VOCAB * EMBED];
__device__ __half   d_wx16[(size_t)G4 * EMBED];
// h as half2 words in mma-A-fragment layout (R8):
//   word(kt, row, tg, j) = kt*512 + row*8 + tg*2 + j ; halves k = kt*16+2tg+8j, +1
__device__ unsigned d_hf[2][64 * 512];
__device__ unsigned d_bar8[SRCLEN * 8];     // per-step spread arrival counters
__device__ unsigned d_xflag[SRCLEN / 2];    // xproj readiness per t-pair (->32)

// ---------------------------------------------------------------------------
__device__ __forceinline__ void mma16(float* c, const uint32_t* a, const uint32_t* b) {
    asm volatile(
        "mma.sync.aligned.m16n8k16.row.col.f32.f16.f16.f32 "
        "{%0,%1,%2,%3}, {%4,%5,%6,%7}, {%8,%9}, {%0,%1,%2,%3};"
        : "+f"(c[0]), "+f"(c[1]), "+f"(c[2]), "+f"(c[3])
        : "r"(a[0]), "r"(a[1]), "r"(a[2]), "r"(a[3]), "r"(b[0]), "r"(b[1]));
}
__device__ __forceinline__ uint32_t h2u(float x, float y) {
    __half2 h = __floats2half2_rn(x, y);
    return *(uint32_t*)&h;
}
__device__ __forceinline__ float tanh_mufu(float x) {
    float y;
    asm("tanh.approx.f32 %0, %1;" : "=f"(y) : "f"(x));
    return y;
}
__device__ __forceinline__ float2 tanh2_f16(float ax, float ay) {
    __half2 hin = __floats2half2_rn(ax, ay);
    uint32_t ui = *(uint32_t*)&hin, uo;
    asm("tanh.approx.f16x2 %0, %1;" : "=r"(uo) : "r"(ui));
    __half2 ho = *(__half2*)&uo;
    return __half22float2(ho);
}
__device__ __forceinline__ unsigned ldflag(const unsigned* p) {
    unsigned v;
    asm volatile("ld.global.cg.u32 %0, [%1];" : "=r"(v) : "l"(p) : "memory");
    return v;
}
__device__ __forceinline__ uint4 ldcg4(const void* p) {
    uint4 v;
    asm volatile("ld.global.cg.v4.u32 {%0,%1,%2,%3}, [%4];"
                 : "=r"(v.x), "=r"(v.y), "=r"(v.z), "=r"(v.w) : "l"(p) : "memory");
    return v;
}

// ---------------------------------------------------------------------------
__global__ void init_kernel() {
    int i = blockIdx.x * blockDim.x + threadIdx.x;
    if (i < 64 * 512)     d_hf[0][i] = 0u;
    if (i < SRCLEN * 8)   d_bar8[i]  = 0u;
    if (i < SRCLEN / 2)   d_xflag[i] = 0u;
}
__global__ void conv_emb_kernel(const float* __restrict__ emb) {
    size_t i = ((size_t)blockIdx.x * blockDim.x + threadIdx.x) * 8;
    float4 a = *(const float4*)(emb + i);
    float4 b = *(const float4*)(emb + i + 4);
    uint4 o = make_uint4(h2u(a.x, a.y), h2u(a.z, a.w), h2u(b.x, b.y), h2u(b.z, b.w));
    *(uint4*)(d_emb16 + i) = o;
}
__global__ void conv_wx_kernel(const float* __restrict__ Wx) {
    size_t i = ((size_t)blockIdx.x * blockDim.x + threadIdx.x) * 8;
    float4 a = *(const float4*)(Wx + i);
    float4 b = *(const float4*)(Wx + i + 4);
    uint4 o = make_uint4(h2u(a.x, a.y), h2u(a.z, a.w), h2u(b.x, b.y), h2u(b.z, b.w));
    *(uint4*)(d_wx16 + i) = o;
}

// ---------------------------------------------------------------------------
// Fused kernel: bids 0..127 = persistent LSTM; bids >=128 = one xproj tile.
// smem sized so 2 CTAs/SM co-reside -> every lstm SM also hosts one xproj CTA.
// ---------------------------------------------------------------------------
#define XP_KW   1040
#define XP_BUF  (2 * XP_KW)
#define PSTR 36
#define FUSED_SMEM_WORDS (16384 + 5 * 64 * PSTR)   // 27904 words = 111616 B

__device__ void xproj_body(uint32_t* xpsm, int* tok,
                           const int* __restrict__ src,
                           const float* __restrict__ bx, int tile)
{
    uint32_t* As = xpsm;
    uint32_t* Bs = xpsm + 2 * XP_BUF;

    const int tid  = threadIdx.x;
    const int lane = tid & 31;
    const int warp = tid >> 5;
    const int wm   = warp & 1;
    const int wn   = warp >> 1;
    const int g    = lane >> 2;
    const int tg   = lane & 3;
    const int yb   = tile >> 5;          // t-pair index 0..511
    const int bm0  = yb * 128;
    const int bn0  = (tile & 31) * 128;

    if (tid < 128) {
        int m = bm0 + tid;
        tok[tid] = src[(m & 63) * SRCLEN + (m >> 6)];
    }
    __syncthreads();

    float acc[4][4][4];
#pragma unroll
    for (int mt = 0; mt < 4; mt++)
#pragma unroll
        for (int nt = 0; nt < 4; nt++)
#pragma unroll
            for (int r = 0; r < 4; r++) acc[mt][nt][r] = 0.0f;

    const int sr2 = tid >> 2;
    const int sq  = tid & 3;
    const int sbase0 = (sq >> 1) * XP_KW + (sq & 1);

#pragma unroll
    for (int it = 0; it < 2; it++) {
        int r = sr2 + it * 64;
        uint4 va = __ldg((const uint4*)(d_emb16 + (size_t)tok[r] * EMBED + sq * 8));
        uint4 vb = __ldg((const uint4*)(d_wx16 + (size_t)(bn0 + r) * EMBED + sq * 8));
        int base = sbase0 + r * 8;
        As[base]     = va.x; As[base + 2] = va.y;
        As[base + 4] = va.z; As[base + 6] = va.w;
        Bs[base]     = vb.x; Bs[base + 2] = vb.y;
        Bs[base + 4] = vb.z; Bs[base + 6] = vb.w;
    }
    __syncthreads();

    uint4 pa[2], pb[2];
    for (int kc = 0; kc < 16; kc++) {
        const int buf = kc & 1;
        if (kc + 1 < 16) {
#pragma unroll
            for (int it = 0; it < 2; it++) {
                int r = sr2 + it * 64;
                pa[it] = __ldg((const uint4*)(d_emb16 + (size_t)tok[r] * EMBED
                                              + (kc + 1) * 32 + sq * 8));
                pb[it] = __ldg((const uint4*)(d_wx16 + (size_t)(bn0 + r) * EMBED
                                              + (kc + 1) * 32 + sq * 8));
            }
        }
        const uint32_t* Ab = As + buf * XP_BUF;
        const uint32_t* Bb = Bs + buf * XP_BUF;
#pragma unroll
        for (int kt = 0; kt < 2; kt++) {
            const int kb = kt * XP_KW;
            uint32_t af[4][4], bf[4][2];
#pragma unroll
            for (int mt = 0; mt < 4; mt++) {
                int r0 = wm * 64 + mt * 16 + g;
                uint2 u0 = *(const uint2*)&Ab[kb + r0 * 8 + tg * 2];
                uint2 u1 = *(const uint2*)&Ab[kb + (r0 + 8) * 8 + tg * 2];
                af[mt][0] = u0.x; af[mt][2] = u0.y;
                af[mt][1] = u1.x; af[mt][3] = u1.y;
            }
#pragma unroll
            for (int nt = 0; nt < 4; nt++) {
                int n0 = wn * 32 + nt * 8 + g;
                uint2 u = *(const uint2*)&Bb[kb + n0 * 8 + tg * 2];
                bf[nt][0] = u.x; bf[nt][1] = u.y;
            }
#pragma unroll
            for (int mt = 0; mt < 4; mt++)
#pragma unroll
                for (int nt = 0; nt < 4; nt++)
                    mma16(acc[mt][nt], af[mt], bf[nt]);
        }
        if (kc + 1 < 16) {
            uint32_t* Ad = As + (buf ^ 1) * XP_BUF;
            uint32_t* Bd = Bs + (buf ^ 1) * XP_BUF;
#pragma unroll
            for (int it = 0; it < 2; it++) {
                int r = sr2 + it * 64;
                int base = sbase0 + r * 8;
                Ad[base]     = pa[it].x; Ad[base + 2] = pa[it].y;
                Ad[base + 4] = pa[it].z; Ad[base + 6] = pa[it].w;
                Bd[base]     = pb[it].x; Bd[base + 2] = pb[it].y;
                Bd[base + 4] = pb[it].z; Bd[base + 6] = pb[it].w;
            }
            __syncthreads();
        }
    }

    // epilogue: + bias, fp16 out (st.cg), then publish readiness of t-pair yb
#pragma unroll
    for (int nt = 0; nt < 4; nt++) {
        int col = bn0 + wn * 32 + nt * 8 + tg * 2;
        float b0 = __ldg(bx + col);
        float b1 = __ldg(bx + col + 1);
#pragma unroll
        for (int mt = 0; mt < 4; mt++)
#pragma unroll
            for (int rr = 0; rr < 2; rr++) {
                int m = bm0 + wm * 64 + mt * 16 + rr * 8 + g;
                __stcg((uint32_t*)(d_xp16 + (size_t)m * G4 + col),
                       h2u(acc[mt][nt][rr * 2] + b0, acc[mt][nt][rr * 2 + 1] + b1));
            }
    }
    __syncthreads();
    if (tid == 0) {
        __threadfence();
        atomicAdd(&d_xflag[yb], 1u);
    }
}

__device__ void lstm_body(float* lsm, const float* __restrict__ Wh,
                          float* __restrict__ out)
{
    uint32_t* Bs  = (uint32_t*)lsm;                 // 16384 words (64 KB)
    float*    psm = lsm + 16384;                    // [5][64][PSTR]

    const int tid  = threadIdx.x;
    const int lane = tid & 31;
    const int warp = tid >> 5;
    const int cta  = blockIdx.x;
    const int wm   = warp & 1;
    const int kh   = warp >> 1;
    const int g    = lane >> 2;
    const int tg   = lane & 3;

    // One-time: Wh slice -> fp16 B-fragment smem
    for (int i = tid; i < 32 * HIDDEN; i += 256) {
        int lc = i >> 10;
        int k  = i & 1023;
        int grow = (lc >> 3) * HIDDEN + cta * 8 + (lc & 7);
        float w = __ldg(Wh + (size_t)grow * HIDDEN + k);
        int kl = k & 15;
        int word = (k >> 4) * 256 + lc * 8 + ((kl & 7) >> 1) * 2 + (kl >> 3);
        ((__half*)Bs)[word * 2 + (k & 1)] = __float2half_rn(w);
    }
    __syncthreads();

    const int eb = tid >> 2;        // epilogue batch row
    const int eu = tid & 3;         // epilogue col-pair (j = 2eu, 2eu+1)
    float cst0 = 0.0f, cst1 = 0.0f;

    const int aoff  = (wm * 32 + g) * 8 + tg * 2;
    const int hword = (cta >> 1) * 512 + eb * 8 + eu * 2 + (cta & 1);

    for (int t = 0; t < SRCLEN; t++) {
        // gate: all 128 CTAs arrived at t-1 AND xproj slice for this t ready
        {
            const unsigned* xf = &d_xflag[t >> 1];
            bool ok;
            do {
                unsigned v = 16u, w = 32u;
                if (lane < 8)
                    v = (t > 0) ? ldflag(&d_bar8[(t - 1) * 8 + lane]) : 16u;
                if (lane == 8)
                    w = ldflag(xf);
                ok = (v >= 16u) && (w >= 32u);
            } while (!__all_sync(0xFFFFFFFFu, ok));
            __threadfence();   // acquire
        }

        // xproj gates (fp16) -> registers (L2-coherent read)
        uint4 xu = ldcg4(d_xp16 + ((size_t)t * BATCH + eb) * G4
                         + eu * HIDDEN + cta * 8);

        float acc[2][4][4];
#pragma unroll
        for (int mt = 0; mt < 2; mt++)
#pragma unroll
            for (int nt = 0; nt < 4; nt++)
#pragma unroll
                for (int r = 0; r < 4; r++) acc[mt][nt][r] = 0.0f;

        const unsigned* hb = d_hf[t & 1];

#pragma unroll 8
        for (int ki = 0; ki < 16; ki++) {
            const int kt = kh * 16 + ki;
            const int kb = kt * 512;
            uint2 u00 = __ldcg((const uint2*)&hb[kb + aoff]);
            uint2 u01 = __ldcg((const uint2*)&hb[kb + aoff + 64]);
            uint2 u10 = __ldcg((const uint2*)&hb[kb + aoff + 128]);
            uint2 u11 = __ldcg((const uint2*)&hb[kb + aoff + 192]);
            uint32_t a0[4] = {u00.x, u01.x, u00.y, u01.y};
            uint32_t a1[4] = {u10.x, u11.x, u10.y, u11.y};
            const uint32_t* bp = Bs + kt * 256;
            uint32_t bf[4][2];
#pragma unroll
            for (int nt = 0; nt < 4; nt++) {
                uint2 u = *(const uint2*)&bp[(nt * 8 + g) * 8 + tg * 2];
                bf[nt][0] = u.x; bf[nt][1] = u.y;
            }
#pragma unroll
            for (int nt = 0; nt < 4; nt++) {
                mma16(acc[0][nt], a0, bf[nt]);
                mma16(acc[1][nt], a1, bf[nt]);
            }
        }

        // all warps publish partials; x (fp16->fp32) -> psm[4]
        {
            float* pp = psm + kh * (64 * PSTR);
#pragma unroll
            for (int mt = 0; mt < 2; mt++)
#pragma unroll
                for (int rr = 0; rr < 2; rr++) {
                    int row = wm * 32 + mt * 16 + rr * 8 + g;
#pragma unroll
                    for (int nt = 0; nt < 4; nt++)
                        *(float2*)&pp[row * PSTR + nt * 8 + tg * 2] =
                            make_float2(acc[mt][nt][rr * 2], acc[mt][nt][rr * 2 + 1]);
                }
            float* xd = psm + 4 * (64 * PSTR) + eb * PSTR + eu * 8;
            float2 x0 = __half22float2(*(__half2*)&xu.x);
            float2 x1 = __half22float2(*(__half2*)&xu.y);
            float2 x2 = __half22float2(*(__half2*)&xu.z);
            float2 x3 = __half22float2(*(__half2*)&xu.w);
            *(float4*)xd       = make_float4(x0.x, x0.y, x1.x, x1.y);
            *(float4*)(xd + 4) = make_float4(x2.x, x2.y, x3.x, x3.y);
        }
        __syncthreads();

        // epilogue: every thread handles (eb, j = 2eu, 2eu+1)
        {
            float2 gv[4];
#pragma unroll
            for (int gg = 0; gg < 4; gg++) {
                float2 s = make_float2(0.0f, 0.0f);
#pragma unroll
                for (int p = 0; p < 5; p++) {
                    float2 q = *(const float2*)&psm[p * (64 * PSTR)
                                + eb * PSTR + gg * 8 + eu * 2];
                    s.x += q.x; s.y += q.y;
                }
                gv[gg] = s;
            }
            float2 ti = tanh2_f16(0.5f * gv[0].x, 0.5f * gv[0].y);
            float2 tf = tanh2_f16(0.5f * gv[1].x, 0.5f * gv[1].y);
            float2 to = tanh2_f16(0.5f * gv[2].x, 0.5f * gv[2].y);
            float2 tgg = tanh2_f16(gv[3].x, gv[3].y);
            float ig0 = fmaf(0.5f, ti.x, 0.5f), ig1 = fmaf(0.5f, ti.y, 0.5f);
            float fg0 = fmaf(0.5f, tf.x, 0.5f), fg1 = fmaf(0.5f, tf.y, 0.5f);
            float og0 = fmaf(0.5f, to.x, 0.5f), og1 = fmaf(0.5f, to.y, 0.5f);

            float c0 = fg0 * cst0 + ig0 * tgg.x;  cst0 = c0;
            float c1 = fg1 * cst1 + ig1 * tgg.y;  cst1 = c1;
            float h0 = og0 * tanh_mufu(c0);
            float h1 = og1 * tanh_mufu(c1);

            __stcg(&d_hf[(t + 1) & 1][hword], h2u(h0, h1));
            if (t == SRCLEN - 1) {
                int col = cta * 8 + eu * 2;
                *(float2*)(out + eb * HIDDEN + col) = make_float2(h0, h1);
                *(float2*)(out + BATCH * HIDDEN + eb * HIDDEN + col) =
                    make_float2(c0, c1);
            }
        }

        // arrival
        __syncthreads();
        if (tid == 0) {
            __threadfence();
            atomicAdd(&d_bar8[t * 8 + (cta & 7)], 1u);
        }
    }
}

__global__ void __launch_bounds__(256, 2) fused_kernel(
    const int* __restrict__ src, const float* __restrict__ bx,
    const float* __restrict__ Wh, float* __restrict__ out)
{
    extern __shared__ float lsm[];
    __shared__ int tok[128];
    if (blockIdx.x < NCTA) {
        lstm_body(lsm, Wh, out);
    } else {
        xproj_body((uint32_t*)lsm, tok, src, bx, blockIdx.x - NCTA);
    }
}

// ---------------------------------------------------------------------------
extern "C" void kernel_launch(void* const* d_in, const int* in_sizes, int n_in,
                              void* d_out, int out_size)
{
    const int*   src = (const int*)d_in[0];
    const float* emb = (const float*)d_in[1];
    const float* Wx  = (const float*)d_in[2];
    const float* bx  = (const float*)d_in[3];
    const float* Wh  = (const float*)d_in[4];
    float*       out = (float*)d_out;

    init_kernel<<<2048, 256>>>();
    conv_emb_kernel<<<(VOCAB * EMBED / 8) / 256, 256>>>(emb);
    conv_wx_kernel<<<(G4 * EMBED / 8) / 256, 256>>>(Wx);

    cudaFuncSetAttribute(fused_kernel, cudaFuncAttributeMaxDynamicSharedMemorySize,
                         FUSED_SMEM_WORDS * 4);
    fused_kernel<<<NCTA + 16384, 256, FUSED_SMEM_WORDS * 4>>>(src, bx, Wh, out);
}

// round 14
// speedup vs baseline: 1.2087x; 1.2087x over previous
#include <cuda_runtime.h>
#include <cuda_fp16.h>
#include <math.h>
#include <stdint.h>

#define VOCAB   32000
#define EMBED   512
#define HIDDEN  1024
#define G4      4096
#define BATCH   64
#define SRCLEN  1024
#define NCTA    128

// Scratch (device globals)
__device__ __half   d_xp16[(size_t)SRCLEN * BATCH * G4];    // (t,b,g) fp16
__device__ __half   d_emb16[(size_t)VOCAB * EMBED];
__device__ __half   d_wx16[(size_t)G4 * EMBED];
// h as half2 words in mma-A-fragment layout (R8):
//   word(kt, row, tg, j) = kt*512 + row*8 + tg*2 + j ; halves k = kt*16+2tg+8j, +1
__device__ unsigned d_hf[2][64 * 512];
// arrival counters: bar8[t*8 + (cta>>4)] -> 16. Counters 2q,2q+1 cover the
// producers of K-quarter q (CTA c produces k in [8c, 8c+8)).
__device__ unsigned d_bar8[SRCLEN * 8];

// ---------------------------------------------------------------------------
__device__ __forceinline__ void mma16(float* c, const uint32_t* a, const uint32_t* b) {
    asm volatile(
        "mma.sync.aligned.m16n8k16.row.col.f32.f16.f16.f32 "
        "{%0,%1,%2,%3}, {%4,%5,%6,%7}, {%8,%9}, {%0,%1,%2,%3};"
        : "+f"(c[0]), "+f"(c[1]), "+f"(c[2]), "+f"(c[3])
        : "r"(a[0]), "r"(a[1]), "r"(a[2]), "r"(a[3]), "r"(b[0]), "r"(b[1]));
}
__device__ __forceinline__ uint32_t h2u(float x, float y) {
    __half2 h = __floats2half2_rn(x, y);
    return *(uint32_t*)&h;
}
__device__ __forceinline__ float tanh_mufu(float x) {
    float y;
    asm("tanh.approx.f32 %0, %1;" : "=f"(y) : "f"(x));
    return y;
}
__device__ __forceinline__ float2 tanh2_f16(float ax, float ay) {
    __half2 hin = __floats2half2_rn(ax, ay);
    uint32_t ui = *(uint32_t*)&hin, uo;
    asm("tanh.approx.f16x2 %0, %1;" : "=r"(uo) : "r"(ui));
    __half2 ho = *(__half2*)&uo;
    return __half22float2(ho);
}
__device__ __forceinline__ unsigned ldflag(const unsigned* p) {
    unsigned v;
    asm volatile("ld.global.cg.u32 %0, [%1];" : "=r"(v) : "l"(p) : "memory");
    return v;
}

// ---------------------------------------------------------------------------
__global__ void init_kernel() {
    int i = blockIdx.x * blockDim.x + threadIdx.x;
    if (i < 64 * 512)   d_hf[0][i] = 0u;
    if (i < SRCLEN * 8) d_bar8[i]  = 0u;
}
__global__ void conv_emb_kernel(const float* __restrict__ emb) {
    size_t i = ((size_t)blockIdx.x * blockDim.x + threadIdx.x) * 8;
    float4 a = *(const float4*)(emb + i);
    float4 b = *(const float4*)(emb + i + 4);
    uint4 o = make_uint4(h2u(a.x, a.y), h2u(a.z, a.w), h2u(b.x, b.y), h2u(b.z, b.w));
    *(uint4*)(d_emb16 + i) = o;
}
__global__ void conv_wx_kernel(const float* __restrict__ Wx) {
    size_t i = ((size_t)blockIdx.x * blockDim.x + threadIdx.x) * 8;
    float4 a = *(const float4*)(Wx + i);
    float4 b = *(const float4*)(Wx + i + 4);
    uint4 o = make_uint4(h2u(a.x, a.y), h2u(a.z, a.w), h2u(b.x, b.y), h2u(b.z, b.w));
    *(uint4*)(d_wx16 + i) = o;
}

// ---------------------------------------------------------------------------
// x_proj (fp16 mma): unchanged from passing R12.
// ---------------------------------------------------------------------------
#define XP_KW   1040
#define XP_BUF  (2 * XP_KW)

__global__ void __launch_bounds__(256, 2) xproj_kernel(
    const int* __restrict__ src, const float* __restrict__ bx)
{
    extern __shared__ uint32_t xpsm[];
    uint32_t* As = xpsm;
    uint32_t* Bs = xpsm + 2 * XP_BUF;
    __shared__ int tok[128];

    const int tid  = threadIdx.x;
    const int lane = tid & 31;
    const int warp = tid >> 5;
    const int wm   = warp & 1;
    const int wn   = warp >> 1;
    const int g    = lane >> 2;
    const int tg   = lane & 3;
    const int bm0  = blockIdx.y * 128;
    const int bn0  = blockIdx.x * 128;

    if (tid < 128) {
        int m = bm0 + tid;
        tok[tid] = src[(m & 63) * SRCLEN + (m >> 6)];
    }
    __syncthreads();

    float acc[4][4][4];
#pragma unroll
    for (int mt = 0; mt < 4; mt++)
#pragma unroll
        for (int nt = 0; nt < 4; nt++)
#pragma unroll
            for (int r = 0; r < 4; r++) acc[mt][nt][r] = 0.0f;

    const int sr2 = tid >> 2;
    const int sq  = tid & 3;
    const int sbase0 = (sq >> 1) * XP_KW + (sq & 1);

#pragma unroll
    for (int it = 0; it < 2; it++) {
        int r = sr2 + it * 64;
        uint4 va = __ldg((const uint4*)(d_emb16 + (size_t)tok[r] * EMBED + sq * 8));
        uint4 vb = __ldg((const uint4*)(d_wx16 + (size_t)(bn0 + r) * EMBED + sq * 8));
        int base = sbase0 + r * 8;
        As[base]     = va.x; As[base + 2] = va.y;
        As[base + 4] = va.z; As[base + 6] = va.w;
        Bs[base]     = vb.x; Bs[base + 2] = vb.y;
        Bs[base + 4] = vb.z; Bs[base + 6] = vb.w;
    }
    __syncthreads();

    uint4 pa[2], pb[2];
    for (int kc = 0; kc < 16; kc++) {
        const int buf = kc & 1;
        if (kc + 1 < 16) {
#pragma unroll
            for (int it = 0; it < 2; it++) {
                int r = sr2 + it * 64;
                pa[it] = __ldg((const uint4*)(d_emb16 + (size_t)tok[r] * EMBED
                                              + (kc + 1) * 32 + sq * 8));
                pb[it] = __ldg((const uint4*)(d_wx16 + (size_t)(bn0 + r) * EMBED
                                              + (kc + 1) * 32 + sq * 8));
            }
        }
        const uint32_t* Ab = As + buf * XP_BUF;
        const uint32_t* Bb = Bs + buf * XP_BUF;
#pragma unroll
        for (int kt = 0; kt < 2; kt++) {
            const int kb = kt * XP_KW;
            uint32_t af[4][4], bf[4][2];
#pragma unroll
            for (int mt = 0; mt < 4; mt++) {
                int r0 = wm * 64 + mt * 16 + g;
                uint2 u0 = *(const uint2*)&Ab[kb + r0 * 8 + tg * 2];
                uint2 u1 = *(const uint2*)&Ab[kb + (r0 + 8) * 8 + tg * 2];
                af[mt][0] = u0.x; af[mt][2] = u0.y;
                af[mt][1] = u1.x; af[mt][3] = u1.y;
            }
#pragma unroll
            for (int nt = 0; nt < 4; nt++) {
                int n0 = wn * 32 + nt * 8 + g;
                uint2 u = *(const uint2*)&Bb[kb + n0 * 8 + tg * 2];
                bf[nt][0] = u.x; bf[nt][1] = u.y;
            }
#pragma unroll
            for (int mt = 0; mt < 4; mt++)
#pragma unroll
                for (int nt = 0; nt < 4; nt++)
                    mma16(acc[mt][nt], af[mt], bf[nt]);
        }
        // stores below hit buf^1 (disjoint); cross-iteration hazard covered by
        // the end-of-iteration sync.
        if (kc + 1 < 16) {
            uint32_t* Ad = As + (buf ^ 1) * XP_BUF;
            uint32_t* Bd = Bs + (buf ^ 1) * XP_BUF;
#pragma unroll
            for (int it = 0; it < 2; it++) {
                int r = sr2 + it * 64;
                int base = sbase0 + r * 8;
                Ad[base]     = pa[it].x; Ad[base + 2] = pa[it].y;
                Ad[base + 4] = pa[it].z; Ad[base + 6] = pa[it].w;
                Bd[base]     = pb[it].x; Bd[base + 2] = pb[it].y;
                Bd[base + 4] = pb[it].z; Bd[base + 6] = pb[it].w;
            }
            __syncthreads();
        }
    }

    // epilogue: + bias, fp16 out
#pragma unroll
    for (int nt = 0; nt < 4; nt++) {
        int col = bn0 + wn * 32 + nt * 8 + tg * 2;
        float b0 = __ldg(bx + col);
        float b1 = __ldg(bx + col + 1);
#pragma unroll
        for (int mt = 0; mt < 4; mt++)
#pragma unroll
            for (int rr = 0; rr < 2; rr++) {
                int m = bm0 + wm * 64 + mt * 16 + rr * 8 + g;
                *(uint32_t*)(d_xp16 + (size_t)m * G4 + col) =
                    h2u(acc[mt][nt][rr * 2] + b0, acc[mt][nt][rr * 2 + 1] + b1);
            }
    }
}

// ---------------------------------------------------------------------------
// Recurrence (fp16 mma), R14 = R12 + quarter-gated mma start.
// Arrival counter group = cta>>4 (16 CTAs each); counters 2q,2q+1 = quarter q.
// Warp kh polls only its quarter's two counters (+fence), so its mma starts
// when its 32 producers are done. h(t+1) writes stay globally gated: the
// pre-epilogue __syncthreads joins all warps = all 4 quarters = 128 arrivals.
// ---------------------------------------------------------------------------
#define PSTR 40
#define LSTM_SMEM_WORDS (16384 + 5 * 64 * PSTR)    // 29184 words = 116736 B

__global__ void __launch_bounds__(256, 1) lstm_kernel(
    const float* __restrict__ Wh, float* __restrict__ out)
{
    extern __shared__ float lsm[];
    uint32_t* Bs  = (uint32_t*)lsm;                 // 16384 words (64 KB)
    float*    psm = lsm + 16384;                    // [5][64][PSTR]

    const int tid  = threadIdx.x;
    const int lane = tid & 31;
    const int warp = tid >> 5;
    const int cta  = blockIdx.x;
    const int wm   = warp & 1;
    const int kh   = warp >> 1;
    const int g    = lane >> 2;
    const int tg   = lane & 3;

    // One-time: Wh slice -> fp16 B-fragment smem
    for (int i = tid; i < 32 * HIDDEN; i += 256) {
        int lc = i >> 10;
        int k  = i & 1023;
        int grow = (lc >> 3) * HIDDEN + cta * 8 + (lc & 7);
        float w = __ldg(Wh + (size_t)grow * HIDDEN + k);
        int kl = k & 15;
        int word = (k >> 4) * 256 + lc * 8 + ((kl & 7) >> 1) * 2 + (kl >> 3);
        ((__half*)Bs)[word * 2 + (k & 1)] = __float2half_rn(w);
    }
    __syncthreads();

    const int eb = tid >> 2;        // epilogue batch row
    const int eu = tid & 3;         // epilogue col-pair (j = 2eu, 2eu+1)
    float cst0 = 0.0f, cst1 = 0.0f;

    const int aoff  = (wm * 32 + g) * 8 + tg * 2;
    const int hword = (cta >> 1) * 512 + eb * 8 + eu * 2 + (cta & 1);

    for (int t = 0; t < SRCLEN; t++) {
        // xproj gates (fp16) -> registers; independent of h, overlaps the spin
        uint4 xu = __ldg((const uint4*)(d_xp16 + ((size_t)t * BATCH + eb) * G4
                                        + eu * HIDDEN + cta * 8));
        // quarter gate: this warp's K quarter (counters 2kh, 2kh+1) published
        if (t > 0) {
            bool ok;
            do {
                unsigned v = (lane < 2)
                    ? ldflag(&d_bar8[(t - 1) * 8 + kh * 2 + lane]) : 16u;
                ok = (v >= 16u);
            } while (!__all_sync(0xFFFFFFFFu, ok));
            __threadfence();   // acquire: order h reads after flag observation
        }

        float acc[2][4][4];
#pragma unroll
        for (int mt = 0; mt < 2; mt++)
#pragma unroll
            for (int nt = 0; nt < 4; nt++)
#pragma unroll
                for (int r = 0; r < 4; r++) acc[mt][nt][r] = 0.0f;

        const unsigned* hb = d_hf[t & 1];

#pragma unroll 8
        for (int ki = 0; ki < 16; ki++) {
            const int kt = kh * 16 + ki;
            const int kb = kt * 512;
            uint2 u00 = __ldcg((const uint2*)&hb[kb + aoff]);
            uint2 u01 = __ldcg((const uint2*)&hb[kb + aoff + 64]);
            uint2 u10 = __ldcg((const uint2*)&hb[kb + aoff + 128]);
            uint2 u11 = __ldcg((const uint2*)&hb[kb + aoff + 192]);
            uint32_t a0[4] = {u00.x, u01.x, u00.y, u01.y};
            uint32_t a1[4] = {u10.x, u11.x, u10.y, u11.y};
            const uint32_t* bp = Bs + kt * 256;
            uint32_t bf[4][2];
#pragma unroll
            for (int nt = 0; nt < 4; nt++) {
                uint2 u = *(const uint2*)&bp[(nt * 8 + g) * 8 + tg * 2];
                bf[nt][0] = u.x; bf[nt][1] = u.y;
            }
#pragma unroll
            for (int nt = 0; nt < 4; nt++) {
                mma16(acc[0][nt], a0, bf[nt]);
                mma16(acc[1][nt], a1, bf[nt]);
            }
        }

        // all warps publish partials; x (fp16->fp32) -> psm[4]
        {
            float* pp = psm + kh * (64 * PSTR);
#pragma unroll
            for (int mt = 0; mt < 2; mt++)
#pragma unroll
                for (int rr = 0; rr < 2; rr++) {
                    int row = wm * 32 + mt * 16 + rr * 8 + g;
#pragma unroll
                    for (int nt = 0; nt < 4; nt++)
                        *(float2*)&pp[row * PSTR + nt * 8 + tg * 2] =
                            make_float2(acc[mt][nt][rr * 2], acc[mt][nt][rr * 2 + 1]);
                }
            float* xd = psm + 4 * (64 * PSTR) + eb * PSTR + eu * 8;
            float2 x0 = __half22float2(*(__half2*)&xu.x);
            float2 x1 = __half22float2(*(__half2*)&xu.y);
            float2 x2 = __half22float2(*(__half2*)&xu.z);
            float2 x3 = __half22float2(*(__half2*)&xu.w);
            *(float4*)xd       = make_float4(x0.x, x0.y, x1.x, x1.y);
            *(float4*)(xd + 4) = make_float4(x2.x, x2.y, x3.x, x3.y);
        }
        __syncthreads();   // joins all 4 quarters' gates -> global WAR cover

        // epilogue: every thread handles (eb, j = 2eu, 2eu+1)
        {
            float2 gv[4];
#pragma unroll
            for (int gg = 0; gg < 4; gg++) {
                float2 s = make_float2(0.0f, 0.0f);
#pragma unroll
                for (int p = 0; p < 5; p++) {
                    float2 q = *(const float2*)&psm[p * (64 * PSTR)
                                + eb * PSTR + gg * 8 + eu * 2];
                    s.x += q.x; s.y += q.y;
                }
                gv[gg] = s;
            }
            float2 ti = tanh2_f16(0.5f * gv[0].x, 0.5f * gv[0].y);
            float2 tf = tanh2_f16(0.5f * gv[1].x, 0.5f * gv[1].y);
            float2 to = tanh2_f16(0.5f * gv[2].x, 0.5f * gv[2].y);
            float2 tgg = tanh2_f16(gv[3].x, gv[3].y);
            float ig0 = fmaf(0.5f, ti.x, 0.5f), ig1 = fmaf(0.5f, ti.y, 0.5f);
            float fg0 = fmaf(0.5f, tf.x, 0.5f), fg1 = fmaf(0.5f, tf.y, 0.5f);
            float og0 = fmaf(0.5f, to.x, 0.5f), og1 = fmaf(0.5f, to.y, 0.5f);

            float c0 = fg0 * cst0 + ig0 * tgg.x;  cst0 = c0;
            float c1 = fg1 * cst1 + ig1 * tgg.y;  cst1 = c1;
            float h0 = og0 * tanh_mufu(c0);
            float h1 = og1 * tanh_mufu(c1);

            __stcg(&d_hf[(t + 1) & 1][hword], h2u(h0, h1));
            if (t == SRCLEN - 1) {
                int col = cta * 8 + eu * 2;
                *(float2*)(out + eb * HIDDEN + col) = make_float2(h0, h1);
                *(float2*)(out + BATCH * HIDDEN + eb * HIDDEN + col) =
                    make_float2(c0, c1);
            }
        }

        // arrival: h(t+1) writes done CTA-wide, then one atomic to group cta>>4
        __syncthreads();
        if (tid == 0) {
            __threadfence();
            atomicAdd(&d_bar8[t * 8 + (cta >> 4)], 1u);
        }
    }
}

// ---------------------------------------------------------------------------
extern "C" void kernel_launch(void* const* d_in, const int* in_sizes, int n_in,
                              void* d_out, int out_size)
{
    const int*   src = (const int*)d_in[0];
    const float* emb = (const float*)d_in[1];
    const float* Wx  = (const float*)d_in[2];
    const float* bx  = (const float*)d_in[3];
    const float* Wh  = (const float*)d_in[4];
    float*       out = (float*)d_out;

    init_kernel<<<128, 256>>>();
    conv_emb_kernel<<<(VOCAB * EMBED / 8) / 256, 256>>>(emb);
    conv_wx_kernel<<<(G4 * EMBED / 8) / 256, 256>>>(Wx);

    cudaFuncSetAttribute(xproj_kernel, cudaFuncAttributeMaxDynamicSharedMemorySize,
                         4 * XP_BUF * 4);
    xproj_kernel<<<dim3(G4 / 128, (SRCLEN * BATCH) / 128), 256, 4 * XP_BUF * 4>>>(
        src, bx);

    cudaFuncSetAttribute(lstm_kernel, cudaFuncAttributeMaxDynamicSharedMemorySize,
                         LSTM_SMEM_WORDS * 4);
    lstm_kernel<<<NCTA, 256, LSTM_SMEM_WORDS * 4>>>(Wh, out);
}

// round 15
// speedup vs baseline: 1.2794x; 1.0584x over previous
#include <cuda_runtime.h>
#include <cuda_fp16.h>
#include <math.h>
#include <stdint.h>

#define VOCAB   32000
#define EMBED   512
#define HIDDEN  1024
#define G4      4096
#define BATCH   64
#define SRCLEN  1024
#define NCTA    128

// Scratch (device globals)
__device__ __half   d_xp16[(size_t)SRCLEN * BATCH * G4];    // (t,b,g) fp16
__device__ __half   d_emb16[(size_t)VOCAB * EMBED];
// Wx pre-converted to mma-B-fragment layout:
//   word(n, kt, tg, j) = (n>>3)*2048 + kt*64 + (n&7)*8 + tg*2 + j
//   where per (n, k): kt=k>>4, tg=(k&7)>>1, j=(k&15)>>3, half=k&1
__device__ unsigned d_wxf[(size_t)(G4 / 8) * 2048];
// h as half2 words in mma-A-fragment layout (R8):
//   word(kt, row, tg, j) = kt*512 + row*8 + tg*2 + j ; halves k = kt*16+2tg+8j, +1
__device__ unsigned d_hf[2][64 * 512];
// arrival counters: bar8[t*8 + (cta>>4)] -> 16. Counters 2q,2q+1 cover the
// producers of K-quarter q (CTA c produces k in [8c, 8c+8)).
__device__ unsigned d_bar8[SRCLEN * 8];

// ---------------------------------------------------------------------------
__device__ __forceinline__ void mma16(float* c, const uint32_t* a, const uint32_t* b) {
    asm volatile(
        "mma.sync.aligned.m16n8k16.row.col.f32.f16.f16.f32 "
        "{%0,%1,%2,%3}, {%4,%5,%6,%7}, {%8,%9}, {%0,%1,%2,%3};"
        : "+f"(c[0]), "+f"(c[1]), "+f"(c[2]), "+f"(c[3])
        : "r"(a[0]), "r"(a[1]), "r"(a[2]), "r"(a[3]), "r"(b[0]), "r"(b[1]));
}
__device__ __forceinline__ uint32_t h2u(float x, float y) {
    __half2 h = __floats2half2_rn(x, y);
    return *(uint32_t*)&h;
}
__device__ __forceinline__ float tanh_mufu(float x) {
    float y;
    asm("tanh.approx.f32 %0, %1;" : "=f"(y) : "f"(x));
    return y;
}
__device__ __forceinline__ float2 tanh2_f16(float ax, float ay) {
    __half2 hin = __floats2half2_rn(ax, ay);
    uint32_t ui = *(uint32_t*)&hin, uo;
    asm("tanh.approx.f16x2 %0, %1;" : "=r"(uo) : "r"(ui));
    __half2 ho = *(__half2*)&uo;
    return __half22float2(ho);
}
__device__ __forceinline__ unsigned ldflag(const unsigned* p) {
    unsigned v;
    asm volatile("ld.global.cg.u32 %0, [%1];" : "=r"(v) : "l"(p) : "memory");
    return v;
}

// ---------------------------------------------------------------------------
__global__ void init_kernel() {
    int i = blockIdx.x * blockDim.x + threadIdx.x;
    if (i < 64 * 512)   d_hf[0][i] = 0u;
    if (i < SRCLEN * 8) d_bar8[i]  = 0u;
}
__global__ void conv_emb_kernel(const float* __restrict__ emb) {
    size_t i = ((size_t)blockIdx.x * blockDim.x + threadIdx.x) * 8;
    float4 a = *(const float4*)(emb + i);
    float4 b = *(const float4*)(emb + i + 4);
    uint4 o = make_uint4(h2u(a.x, a.y), h2u(a.z, a.w), h2u(b.x, b.y), h2u(b.z, b.w));
    *(uint4*)(d_emb16 + i) = o;
}
// Wx (row-major fp32, [4096, 512]) -> fragment-layout fp16 d_wxf
__global__ void conv_wx_kernel(const float* __restrict__ Wx) {
    size_t i = ((size_t)blockIdx.x * blockDim.x + threadIdx.x) * 8;
    int n  = (int)(i >> 9);          // gate row 0..4095
    int k0 = (int)(i & 511);         // 8-aligned k
    float4 a = *(const float4*)(Wx + i);
    float4 b = *(const float4*)(Wx + i + 4);
    unsigned base = (unsigned)((n >> 3) * 2048 + (k0 >> 4) * 64
                               + (n & 7) * 8 + ((k0 & 15) >> 3));
    d_wxf[base + 0] = h2u(a.x, a.y);     // tg=(k0&7)>>1 = 0
    d_wxf[base + 2] = h2u(a.z, a.w);     // tg=1
    d_wxf[base + 4] = h2u(b.x, b.y);     // tg=2
    d_wxf[base + 6] = h2u(b.z, b.w);     // tg=3
}

// ---------------------------------------------------------------------------
// x_proj (fp16 mma), R15: B (Wx) fragments straight from gmem (L1/L2-cached),
// B smem tile + staging deleted -> ~1/3 less LDS traffic in an L1-bound kernel.
// Grid: x = m-tile (fast) so co-resident CTAs share the same Wx panel.
// ---------------------------------------------------------------------------
#define XP_KW   1040
#define XP_BUF  (2 * XP_KW)

__global__ void __launch_bounds__(256, 2) xproj_kernel(
    const int* __restrict__ src, const float* __restrict__ bx)
{
    extern __shared__ uint32_t xpsm[];
    uint32_t* As = xpsm;                 // [2][XP_BUF]
    __shared__ int tok[128];

    const int tid  = threadIdx.x;
    const int lane = tid & 31;
    const int warp = tid >> 5;
    const int wm   = warp & 1;
    const int wn   = warp >> 1;
    const int g    = lane >> 2;
    const int tg   = lane & 3;
    const int bm0  = blockIdx.x * 128;   // m fast-varying
    const int bn0  = blockIdx.y * 128;

    if (tid < 128) {
        int m = bm0 + tid;
        tok[tid] = src[(m & 63) * SRCLEN + (m >> 6)];
    }
    __syncthreads();

    float acc[4][4][4];
#pragma unroll
    for (int mt = 0; mt < 4; mt++)
#pragma unroll
        for (int nt = 0; nt < 4; nt++)
#pragma unroll
            for (int r = 0; r < 4; r++) acc[mt][nt][r] = 0.0f;

    // B fragment gmem bases per nt (word units)
    unsigned gbase[4];
#pragma unroll
    for (int nt = 0; nt < 4; nt++)
        gbase[nt] = (unsigned)(((bn0 >> 3) + wn * 4 + nt) * 2048 + g * 8 + tg * 2);

    const int sr2 = tid >> 2;
    const int sq  = tid & 3;
    const int sbase0 = (sq >> 1) * XP_KW + (sq & 1);

    // stage A chunk 0
#pragma unroll
    for (int it = 0; it < 2; it++) {
        int r = sr2 + it * 64;
        uint4 va = __ldg((const uint4*)(d_emb16 + (size_t)tok[r] * EMBED + sq * 8));
        int base = sbase0 + r * 8;
        As[base]     = va.x; As[base + 2] = va.y;
        As[base + 4] = va.z; As[base + 6] = va.w;
    }
    __syncthreads();

    uint4 pa[2];
    for (int kc = 0; kc < 16; kc++) {
        const int buf = kc & 1;
        if (kc + 1 < 16) {
#pragma unroll
            for (int it = 0; it < 2; it++) {
                int r = sr2 + it * 64;
                pa[it] = __ldg((const uint4*)(d_emb16 + (size_t)tok[r] * EMBED
                                              + (kc + 1) * 32 + sq * 8));
            }
        }
        const uint32_t* Ab = As + buf * XP_BUF;
#pragma unroll
        for (int kt = 0; kt < 2; kt++) {
            const int kb  = kt * XP_KW;
            const int ktg = kc * 2 + kt;
            uint32_t af[4][4], bf[4][2];
#pragma unroll
            for (int mt = 0; mt < 4; mt++) {
                int r0 = wm * 64 + mt * 16 + g;
                uint2 u0 = *(const uint2*)&Ab[kb + r0 * 8 + tg * 2];
                uint2 u1 = *(const uint2*)&Ab[kb + (r0 + 8) * 8 + tg * 2];
                af[mt][0] = u0.x; af[mt][2] = u0.y;
                af[mt][1] = u1.x; af[mt][3] = u1.y;
            }
#pragma unroll
            for (int nt = 0; nt < 4; nt++) {
                uint2 u = __ldg((const uint2*)&d_wxf[gbase[nt] + ktg * 64]);
                bf[nt][0] = u.x; bf[nt][1] = u.y;
            }
#pragma unroll
            for (int mt = 0; mt < 4; mt++)
#pragma unroll
                for (int nt = 0; nt < 4; nt++)
                    mma16(acc[mt][nt], af[mt], bf[nt]);
        }
        if (kc + 1 < 16) {
            uint32_t* Ad = As + (buf ^ 1) * XP_BUF;
#pragma unroll
            for (int it = 0; it < 2; it++) {
                int r = sr2 + it * 64;
                int base = sbase0 + r * 8;
                Ad[base]     = pa[it].x; Ad[base + 2] = pa[it].y;
                Ad[base + 4] = pa[it].z; Ad[base + 6] = pa[it].w;
            }
            __syncthreads();
        }
    }

    // epilogue: + bias, fp16 out
#pragma unroll
    for (int nt = 0; nt < 4; nt++) {
        int col = bn0 + wn * 32 + nt * 8 + tg * 2;
        float b0 = __ldg(bx + col);
        float b1 = __ldg(bx + col + 1);
#pragma unroll
        for (int mt = 0; mt < 4; mt++)
#pragma unroll
            for (int rr = 0; rr < 2; rr++) {
                int m = bm0 + wm * 64 + mt * 16 + rr * 8 + g;
                *(uint32_t*)(d_xp16 + (size_t)m * G4 + col) =
                    h2u(acc[mt][nt][rr * 2] + b0, acc[mt][nt][rr * 2 + 1] + b1);
            }
    }
}

// ---------------------------------------------------------------------------
// Recurrence (fp16 mma): frozen R14 (quarter-gated start, proven).
// ---------------------------------------------------------------------------
#define PSTR 40
#define LSTM_SMEM_WORDS (16384 + 5 * 64 * PSTR)    // 29184 words = 116736 B

__global__ void __launch_bounds__(256, 1) lstm_kernel(
    const float* __restrict__ Wh, float* __restrict__ out)
{
    extern __shared__ float lsm[];
    uint32_t* Bs  = (uint32_t*)lsm;                 // 16384 words (64 KB)
    float*    psm = lsm + 16384;                    // [5][64][PSTR]

    const int tid  = threadIdx.x;
    const int lane = tid & 31;
    const int warp = tid >> 5;
    const int cta  = blockIdx.x;
    const int wm   = warp & 1;
    const int kh   = warp >> 1;
    const int g    = lane >> 2;
    const int tg   = lane & 3;

    // One-time: Wh slice -> fp16 B-fragment smem
    for (int i = tid; i < 32 * HIDDEN; i += 256) {
        int lc = i >> 10;
        int k  = i & 1023;
        int grow = (lc >> 3) * HIDDEN + cta * 8 + (lc & 7);
        float w = __ldg(Wh + (size_t)grow * HIDDEN + k);
        int kl = k & 15;
        int word = (k >> 4) * 256 + lc * 8 + ((kl & 7) >> 1) * 2 + (kl >> 3);
        ((__half*)Bs)[word * 2 + (k & 1)] = __float2half_rn(w);
    }
    __syncthreads();

    const int eb = tid >> 2;        // epilogue batch row
    const int eu = tid & 3;         // epilogue col-pair (j = 2eu, 2eu+1)
    float cst0 = 0.0f, cst1 = 0.0f;

    const int aoff  = (wm * 32 + g) * 8 + tg * 2;
    const int hword = (cta >> 1) * 512 + eb * 8 + eu * 2 + (cta & 1);

    for (int t = 0; t < SRCLEN; t++) {
        // xproj gates (fp16) -> registers; independent of h, overlaps the spin
        uint4 xu = __ldg((const uint4*)(d_xp16 + ((size_t)t * BATCH + eb) * G4
                                        + eu * HIDDEN + cta * 8));
        // quarter gate: this warp's K quarter (counters 2kh, 2kh+1) published
        if (t > 0) {
            bool ok;
            do {
                unsigned v = (lane < 2)
                    ? ldflag(&d_bar8[(t - 1) * 8 + kh * 2 + lane]) : 16u;
                ok = (v >= 16u);
            } while (!__all_sync(0xFFFFFFFFu, ok));
            __threadfence();   // acquire
        }

        float acc[2][4][4];
#pragma unroll
        for (int mt = 0; mt < 2; mt++)
#pragma unroll
            for (int nt = 0; nt < 4; nt++)
#pragma unroll
                for (int r = 0; r < 4; r++) acc[mt][nt][r] = 0.0f;

        const unsigned* hb = d_hf[t & 1];

#pragma unroll 8
        for (int ki = 0; ki < 16; ki++) {
            const int kt = kh * 16 + ki;
            const int kb = kt * 512;
            uint2 u00 = __ldcg((const uint2*)&hb[kb + aoff]);
            uint2 u01 = __ldcg((const uint2*)&hb[kb + aoff + 64]);
            uint2 u10 = __ldcg((const uint2*)&hb[kb + aoff + 128]);
            uint2 u11 = __ldcg((const uint2*)&hb[kb + aoff + 192]);
            uint32_t a0[4] = {u00.x, u01.x, u00.y, u01.y};
            uint32_t a1[4] = {u10.x, u11.x, u10.y, u11.y};
            const uint32_t* bp = Bs + kt * 256;
            uint32_t bf[4][2];
#pragma unroll
            for (int nt = 0; nt < 4; nt++) {
                uint2 u = *(const uint2*)&bp[(nt * 8 + g) * 8 + tg * 2];
                bf[nt][0] = u.x; bf[nt][1] = u.y;
            }
#pragma unroll
            for (int nt = 0; nt < 4; nt++) {
                mma16(acc[0][nt], a0, bf[nt]);
                mma16(acc[1][nt], a1, bf[nt]);
            }
        }

        // all warps publish partials; x (fp16->fp32) -> psm[4]
        {
            float* pp = psm + kh * (64 * PSTR);
#pragma unroll
            for (int mt = 0; mt < 2; mt++)
#pragma unroll
                for (int rr = 0; rr < 2; rr++) {
                    int row = wm * 32 + mt * 16 + rr * 8 + g;
#pragma unroll
                    for (int nt = 0; nt < 4; nt++)
                        *(float2*)&pp[row * PSTR + nt * 8 + tg * 2] =
                            make_float2(acc[mt][nt][rr * 2], acc[mt][nt][rr * 2 + 1]);
                }
            float* xd = psm + 4 * (64 * PSTR) + eb * PSTR + eu * 8;
            float2 x0 = __half22float2(*(__half2*)&xu.x);
            float2 x1 = __half22float2(*(__half2*)&xu.y);
            float2 x2 = __half22float2(*(__half2*)&xu.z);
            float2 x3 = __half22float2(*(__half2*)&xu.w);
            *(float4*)xd       = make_float4(x0.x, x0.y, x1.x, x1.y);
            *(float4*)(xd + 4) = make_float4(x2.x, x2.y, x3.x, x3.y);
        }
        __syncthreads();   // joins all 4 quarters' gates -> global WAR cover

        // epilogue: every thread handles (eb, j = 2eu, 2eu+1)
        {
            float2 gv[4];
#pragma unroll
            for (int gg = 0; gg < 4; gg++) {
                float2 s = make_float2(0.0f, 0.0f);
#pragma unroll
                for (int p = 0; p < 5; p++) {
                    float2 q = *(const float2*)&psm[p * (64 * PSTR)
                                + eb * PSTR + gg * 8 + eu * 2];
                    s.x += q.x; s.y += q.y;
                }
                gv[gg] = s;
            }
            float2 ti = tanh2_f16(0.5f * gv[0].x, 0.5f * gv[0].y);
            float2 tf = tanh2_f16(0.5f * gv[1].x, 0.5f * gv[1].y);
            float2 to = tanh2_f16(0.5f * gv[2].x, 0.5f * gv[2].y);
            float2 tgg = tanh2_f16(gv[3].x, gv[3].y);
            float ig0 = fmaf(0.5f, ti.x, 0.5f), ig1 = fmaf(0.5f, ti.y, 0.5f);
            float fg0 = fmaf(0.5f, tf.x, 0.5f), fg1 = fmaf(0.5f, tf.y, 0.5f);
            float og0 = fmaf(0.5f, to.x, 0.5f), og1 = fmaf(0.5f, to.y, 0.5f);

            float c0 = fg0 * cst0 + ig0 * tgg.x;  cst0 = c0;
            float c1 = fg1 * cst1 + ig1 * tgg.y;  cst1 = c1;
            float h0 = og0 * tanh_mufu(c0);
            float h1 = og1 * tanh_mufu(c1);

            __stcg(&d_hf[(t + 1) & 1][hword], h2u(h0, h1));
            if (t == SRCLEN - 1) {
                int col = cta * 8 + eu * 2;
                *(float2*)(out + eb * HIDDEN + col) = make_float2(h0, h1);
                *(float2*)(out + BATCH * HIDDEN + eb * HIDDEN + col) =
                    make_float2(c0, c1);
            }
        }

        // arrival: h(t+1) writes done CTA-wide, then one atomic to group cta>>4
        __syncthreads();
        if (tid == 0) {
            __threadfence();
            atomicAdd(&d_bar8[t * 8 + (cta >> 4)], 1u);
        }
    }
}

// ---------------------------------------------------------------------------
extern "C" void kernel_launch(void* const* d_in, const int* in_sizes, int n_in,
                              void* d_out, int out_size)
{
    const int*   src = (const int*)d_in[0];
    const float* emb = (const float*)d_in[1];
    const float* Wx  = (const float*)d_in[2];
    const float* bx  = (const float*)d_in[3];
    const float* Wh  = (const float*)d_in[4];
    float*       out = (float*)d_out;

    init_kernel<<<128, 256>>>();
    conv_emb_kernel<<<(VOCAB * EMBED / 8) / 256, 256>>>(emb);
    conv_wx_kernel<<<(G4 * EMBED / 8) / 256, 256>>>(Wx);

    cudaFuncSetAttribute(xproj_kernel, cudaFuncAttributeMaxDynamicSharedMemorySize,
                         2 * XP_BUF * 4);
    xproj_kernel<<<dim3((SRCLEN * BATCH) / 128, G4 / 128), 256, 2 * XP_BUF * 4>>>(
        src, bx);

    cudaFuncSetAttribute(lstm_kernel, cudaFuncAttributeMaxDynamicSharedMemorySize,
                         LSTM_SMEM_WORDS * 4);
    lstm_kernel<<<NCTA, 256, LSTM_SMEM_WORDS * 4>>>(Wh, out);
}